// round 13
// baseline (speedup 1.0000x reference)
#include <cuda_runtime.h>
#include <cuda_bf16.h>
#include <math.h>
#include <stdint.h>

#define NB    64
#define TFULL 256
#define TT    255
#define NT    (NB * TT)        // 16320 token rows
#define VOCAB 10000
#define DFEAT 1280
#define WDIM  256
#define HDIM  512

// ---- loss kernel tiling ----
#define LDA      520                 // bf16 elems per A smem row (512 + 8 pad)
#define LDB      72                  // bf16 elems per B smem row (64 + 8 pad)
#define KSTAGE   64
#define NSTAGES  (HDIM / KSTAGE)     // 8
#define BSTRIDE  (128 * LDB)         // bf16 elems per B stage
#define NVT      ((VOCAB + 127) / 128)   // 79 vocab tiles
#define DSMEM    (128 * LDA * 2 + 2 * 128 * LDB * 2)   // 169984 bytes

// ---- rnn: 16 rowgroups (4 rows) x 8 colgroups (64 cols); cluster = 8 CTAs (one rowgroup)
#define RG_ROWS  4
#define CG_COLS  64

// ---------------- scratch (static device globals; no allocations) ----------------
__device__ float g_h[2][NB * HDIM];                       // [0] = h0 (input to scan)
__device__ float g_xW[NT * HDIM];                         // emb @ Wx + b
__device__ __align__(256) __nv_bfloat16 g_hsb[NT * HDIM]; // hidden states, bf16
__device__ __align__(256) __nv_bfloat16 g_Wb[VOCAB * HDIM]; // W_out^T, bf16, [v][k]

// ---------------- small asm helpers ----------------
__device__ __forceinline__ void cp16(uint32_t dst, const void* src) {
    asm volatile("cp.async.cg.shared.global [%0], [%1], 16;" :: "r"(dst), "l"(src));
}
__device__ __forceinline__ void cp_commit() { asm volatile("cp.async.commit_group;"); }
template <int N>
__device__ __forceinline__ void cp_wait() { asm volatile("cp.async.wait_group %0;" :: "n"(N)); }

__device__ __forceinline__ void ldsm4(uint32_t& r0, uint32_t& r1, uint32_t& r2, uint32_t& r3,
                                      uint32_t addr) {
    asm volatile("ldmatrix.sync.aligned.m8n8.x4.shared.b16 {%0,%1,%2,%3}, [%4];"
                 : "=r"(r0), "=r"(r1), "=r"(r2), "=r"(r3) : "r"(addr));
}
__device__ __forceinline__ void mma16816(float* c,
                                         uint32_t a0, uint32_t a1, uint32_t a2, uint32_t a3,
                                         uint32_t b0, uint32_t b1) {
    asm volatile("mma.sync.aligned.m16n8k16.row.col.f32.bf16.bf16.f32 "
                 "{%0,%1,%2,%3}, {%4,%5,%6,%7}, {%8,%9}, {%0,%1,%2,%3};"
                 : "+f"(c[0]), "+f"(c[1]), "+f"(c[2]), "+f"(c[3])
                 : "r"(a0), "r"(a1), "r"(a2), "r"(a3), "r"(b0), "r"(b1));
}
#define FFMA2(acc, a, b) \
    asm("fma.rn.f32x2 %0, %1, %2, %0;" : "+l"(acc) : "l"(a), "l"(b))

// ---------------- init ----------------
__global__ void init_kernel(float* out) {
    if (threadIdx.x == 0) out[0] = 0.0f;
}

// ---------------- kernel 1: h0 = feat @ W_proj + b_proj ----------------
__global__ void __launch_bounds__(256) h0_kernel(const float* __restrict__ feat,
                                                 const float* __restrict__ Wp,
                                                 const float* __restrict__ bp) {
    __shared__ float As[32][20];
    __shared__ float Bs[32][68];
    int tid = threadIdx.x;
    int r0 = blockIdx.x * 16;
    int c0 = blockIdx.y * 64;
    int r = tid >> 4;
    int cg = tid & 15;
    float acc0 = 0.f, acc1 = 0.f, acc2 = 0.f, acc3 = 0.f;

    for (int kc = 0; kc < DFEAT; kc += 32) {
        __syncthreads();
        if (tid < 128) {
            int row = tid >> 3, kq = (tid & 7) << 2;
            float4 v = *reinterpret_cast<const float4*>(feat + (size_t)(r0 + row) * DFEAT + kc + kq);
            As[kq + 0][row] = v.x; As[kq + 1][row] = v.y;
            As[kq + 2][row] = v.z; As[kq + 3][row] = v.w;
        }
        for (int u = tid; u < 512; u += 256) {
            int k = u >> 4, jq = (u & 15) << 2;
            *reinterpret_cast<float4*>(&Bs[k][jq]) =
                *reinterpret_cast<const float4*>(Wp + (size_t)(kc + k) * HDIM + c0 + jq);
        }
        __syncthreads();
        #pragma unroll
        for (int k = 0; k < 32; k++) {
            float a = As[k][r];
            float4 bv = *reinterpret_cast<const float4*>(&Bs[k][cg << 2]);
            acc0 = fmaf(a, bv.x, acc0); acc1 = fmaf(a, bv.y, acc1);
            acc2 = fmaf(a, bv.z, acc2); acc3 = fmaf(a, bv.w, acc3);
        }
    }
    int col = c0 + (cg << 2);
    float4 bb = *reinterpret_cast<const float4*>(bp + col);
    float4 o;
    o.x = acc0 + bb.x; o.y = acc1 + bb.y; o.z = acc2 + bb.z; o.w = acc3 + bb.w;
    *reinterpret_cast<float4*>(&g_h[0][(r0 + r) * HDIM + col]) = o;
}

// ---------------- kernel 2: xW = gather(W_embed, cap_in) @ Wx + b ----------------
__global__ void __launch_bounds__(256) xw_kernel(const int* __restrict__ captions,
                                                 const float* __restrict__ Wemb,
                                                 const float* __restrict__ Wx,
                                                 const float* __restrict__ bias) {
    __shared__ float As[32][68];
    __shared__ float Bs[32][132];
    __shared__ const float* Arow[64];
    int tid = threadIdx.x;
    int i0 = blockIdx.x * 64;
    int c0 = blockIdx.y * 128;
    if (tid < 64) {
        int i = i0 + tid;
        int n = i / TT;
        int t = i - n * TT;
        int idx = captions[n * TFULL + t];
        Arow[tid] = Wemb + (size_t)idx * WDIM;
    }
    int tr = tid >> 4, tc = tid & 15;
    float acc[4][8];
    #pragma unroll
    for (int a = 0; a < 4; a++)
        #pragma unroll
        for (int b2 = 0; b2 < 8; b2++) acc[a][b2] = 0.f;

    for (int kc = 0; kc < WDIM; kc += 32) {
        __syncthreads();
        for (int u = tid; u < 512; u += 256) {
            int row = u >> 3, kq = (u & 7) << 2;
            float4 v = *reinterpret_cast<const float4*>(Arow[row] + kc + kq);
            As[kq + 0][row] = v.x; As[kq + 1][row] = v.y;
            As[kq + 2][row] = v.z; As[kq + 3][row] = v.w;
        }
        for (int u = tid; u < 1024; u += 256) {
            int k = u >> 5, jq = (u & 31) << 2;
            *reinterpret_cast<float4*>(&Bs[k][jq]) =
                *reinterpret_cast<const float4*>(Wx + (size_t)(kc + k) * HDIM + c0 + jq);
        }
        __syncthreads();
        #pragma unroll
        for (int k = 0; k < 32; k++) {
            float4 av = *reinterpret_cast<const float4*>(&As[k][tr << 2]);
            float4 bv0 = *reinterpret_cast<const float4*>(&Bs[k][tc << 3]);
            float4 bv1 = *reinterpret_cast<const float4*>(&Bs[k][(tc << 3) + 4]);
            float aa[4] = {av.x, av.y, av.z, av.w};
            float bb[8] = {bv0.x, bv0.y, bv0.z, bv0.w, bv1.x, bv1.y, bv1.z, bv1.w};
            #pragma unroll
            for (int rr = 0; rr < 4; rr++)
                #pragma unroll
                for (int jj = 0; jj < 8; jj++)
                    acc[rr][jj] = fmaf(aa[rr], bb[jj], acc[rr][jj]);
        }
    }
    int rowb = i0 + (tr << 2);
    int cb = c0 + (tc << 3);
    float4 b0 = *reinterpret_cast<const float4*>(bias + cb);
    float4 b1 = *reinterpret_cast<const float4*>(bias + cb + 4);
    #pragma unroll
    for (int rr = 0; rr < 4; rr++) {
        float* dst = g_xW + (size_t)(rowb + rr) * HDIM + cb;
        float4 o0, o1;
        o0.x = acc[rr][0] + b0.x; o0.y = acc[rr][1] + b0.y;
        o0.z = acc[rr][2] + b0.z; o0.w = acc[rr][3] + b0.w;
        o1.x = acc[rr][4] + b1.x; o1.y = acc[rr][5] + b1.y;
        o1.z = acc[rr][6] + b1.z; o1.w = acc[rr][7] + b1.w;
        *reinterpret_cast<float4*>(dst) = o0;
        *reinterpret_cast<float4*>(dst + 4) = o1;
    }
}

// ---------------- kernel 2b: W_out [k][v] fp32 -> g_Wb [v][k] bf16 ----------------
__global__ void __launch_bounds__(256) wtrans_kernel(const float* __restrict__ Wout) {
    __shared__ float tile[32][33];
    int v0 = blockIdx.x * 32, k0 = blockIdx.y * 32;
    int tx = threadIdx.x & 31, ty = threadIdx.x >> 5;
    for (int r = ty; r < 32; r += 8) {
        int vv = v0 + tx;
        tile[r][tx] = (vv < VOCAB) ? Wout[(size_t)(k0 + r) * VOCAB + vv] : 0.f;
    }
    __syncthreads();
    for (int r = ty; r < 32; r += 8) {
        int vv = v0 + r;
        if (vv < VOCAB)
            g_Wb[(size_t)vv * HDIM + k0 + tx] = __float2bfloat16(tile[tx][r]);
    }
}

// ---------------- kernel 3: RNN scan via clusters + DSMEM ----------------
// 128 blocks x 512 threads; cluster of 8 CTAs = one rowgroup (4 rows), CTA = 64 cols.
// h lives ONLY in smem (double-buffered). Each step: compute partials from local
// hsm[buf] (Wh in regs, FFMA2), reduce, push own 4x64 slice into ALL 8 cluster CTAs'
// hsm[buf^1] (st.shared::cluster), then cluster.sync. No global h traffic, no L2 polling.
__global__ void __launch_bounds__(512, 1) __cluster_dims__(8, 1, 1)
rnn_kernel(const float* __restrict__ Wh) {
    __shared__ float hsm[2][RG_ROWS * HDIM];        // 16 KB (double buffer)
    __shared__ float part[RG_ROWS * 2 * 8 * 32];    // [row][ch][ks][lane] 8 KB
    int tid = threadIdx.x;
    int cg = blockIdx.x & 7;          // ctarank within cluster
    int rg = blockIdx.x >> 3;         // rowgroup
    int r0 = rg * RG_ROWS;
    int lane = tid & 31;
    int wid = tid >> 5;               // 16 warps
    int ks = wid & 7;                 // k-slice (64 wide)
    int ch = wid >> 3;                // col half (32 cols)
    int gcol = cg * CG_COLS + ch * 32 + lane;

    // Wh slice into packed f32x2 registers: Wh[ks*64 .. +64][gcol]
    unsigned long long wreg[32];
    #pragma unroll
    for (int j2 = 0; j2 < 32; ++j2) {
        int k = ks * 64 + j2 * 2;
        float lo = Wh[(size_t)k * HDIM + gcol];
        float hi = Wh[(size_t)(k + 1) * HDIM + gcol];
        asm("mov.b64 %0, {%1, %2};" : "=l"(wreg[j2]) : "f"(lo), "f"(hi));
    }

    // fill hsm[0] with h0 rows r0..r0+RG_ROWS (own copy; peers fill their own)
    {
        const float4* src = reinterpret_cast<const float4*>(g_h[0] + (size_t)r0 * HDIM);
        float4* dst = reinterpret_cast<float4*>(hsm[0]);
        dst[tid] = src[tid];          // 512 float4 = 4x512 floats
    }
    __syncthreads();

    // reduce/push identities (first 256 threads own one output each)
    int orow = tid >> 6;              // 0..3
    int ocol = tid & 63;              // 0..63
    int och = ocol >> 5, olane = ocol & 31;
    int ogcol = cg * CG_COLS + ocol;
    uint32_t hsm_u = (uint32_t)__cvta_generic_to_shared(&hsm[0][0]);

    for (int t = 0; t < TT; ++t) {
        int buf = t & 1;
        float xw = 0.f;
        if (tid < 256)
            xw = g_xW[((size_t)(r0 + orow) * TT + t) * HDIM + ogcol];

        const float* hb = hsm[buf];
        #pragma unroll
        for (int r = 0; r < RG_ROWS; ++r) {
            const ulonglong2* hp = reinterpret_cast<const ulonglong2*>(hb + r * HDIM + ks * 64);
            unsigned long long a0 = 0ull, a1 = 0ull, a2 = 0ull, a3 = 0ull;
            #pragma unroll
            for (int jj = 0; jj < 16; jj += 2) {
                ulonglong2 v0 = hp[jj];
                ulonglong2 v1 = hp[jj + 1];
                FFMA2(a0, v0.x, wreg[2 * jj + 0]);
                FFMA2(a1, v0.y, wreg[2 * jj + 1]);
                FFMA2(a2, v1.x, wreg[2 * jj + 2]);
                FFMA2(a3, v1.y, wreg[2 * jj + 3]);
            }
            unsigned long long s01, s23, s;
            asm("add.rn.f32x2 %0, %1, %2;" : "=l"(s01) : "l"(a0), "l"(a1));
            asm("add.rn.f32x2 %0, %1, %2;" : "=l"(s23) : "l"(a2), "l"(a3));
            asm("add.rn.f32x2 %0, %1, %2;" : "=l"(s)   : "l"(s01), "l"(s23));
            float lo, hi;
            asm("mov.b64 {%0, %1}, %2;" : "=f"(lo), "=f"(hi) : "l"(s));
            part[((r * 2 + ch) * 8 + ks) * 32 + lane] = lo + hi;
        }
        __syncthreads();

        if (tid < 256) {
            float acc = 0.f;
            #pragma unroll
            for (int k2 = 0; k2 < 8; ++k2)
                acc += part[((orow * 2 + och) * 8 + k2) * 32 + olane];
            float hn = tanhf(acc + xw);
            uint32_t hnb = __float_as_uint(hn);
            // push into every cluster CTA's hsm[buf^1] at the same offset
            uint32_t loff = hsm_u + (uint32_t)(((buf ^ 1) * RG_ROWS * HDIM) + orow * HDIM + ogcol) * 4u;
            #pragma unroll
            for (int p = 0; p < 8; ++p) {
                uint32_t raddr;
                asm("mapa.shared::cluster.u32 %0, %1, %2;" : "=r"(raddr) : "r"(loff), "r"(p));
                asm volatile("st.shared::cluster.b32 [%0], %1;" :: "r"(raddr), "r"(hnb) : "memory");
            }
            g_hsb[((size_t)(r0 + orow) * TT + t) * HDIM + ogcol] = __float2bfloat16(hn);
        }

        // cluster-wide barrier: orders remote stores (arrive=release, wait=acquire)
        asm volatile("barrier.cluster.arrive.aligned;" ::: "memory");
        asm volatile("barrier.cluster.wait.aligned;" ::: "memory");
    }
}

// ---------------- kernel 4: bf16 HMMA scores GEMM + exp-sum epilogue ----------------
extern __shared__ char dsm[];

__global__ void __launch_bounds__(256, 1) loss_kernel(const float* __restrict__ bout,
                                                      const int* __restrict__ captions,
                                                      float* __restrict__ out) {
    __nv_bfloat16* sA = reinterpret_cast<__nv_bfloat16*>(dsm);               // 128 x LDA
    __nv_bfloat16* sB = reinterpret_cast<__nv_bfloat16*>(dsm + 128 * LDA * 2); // 2 x 128 x LDB
    __shared__ float biasS[128];
    __shared__ float s_red[256];
    __shared__ float warp_sum[8];

    int tid = threadIdx.x;
    int lane = tid & 31, w = tid >> 5;
    int wm = w >> 1, wn = w & 1;
    int g = lane >> 2, tig = lane & 3;
    int i0 = blockIdx.x * 128;

    const char* hsb_base = reinterpret_cast<const char*>(g_hsb);
    for (int u = tid; u < 8192; u += 256) {
        int r = u >> 6, q = u & 63;
        int gi = i0 + r; if (gi >= NT) gi = NT - 1;
        float4 v = *reinterpret_cast<const float4*>(hsb_base + ((size_t)gi * HDIM + q * 8) * 2);
        *reinterpret_cast<float4*>(reinterpret_cast<char*>(sA) + (size_t)r * LDA * 2 + q * 16) = v;
    }
    __syncthreads();

    uint32_t sA_u = (uint32_t)__cvta_generic_to_shared(sA);
    uint32_t sB_u = (uint32_t)__cvta_generic_to_shared(sB);

    int j = lane >> 3, i8 = lane & 7;
    int a_row    = wm * 32 + (j & 1) * 8 + i8;
    int a_coloff = (j >> 1) * 8;
    int b_rowoff = (j >> 1) * 8 + i8;
    int b_coloff = (j & 1) * 8;

    float s_slot[4] = {0.f, 0.f, 0.f, 0.f};

    for (int vt = 0; vt < NVT; ++vt) {
        int v0 = vt * 128;
        for (int u2 = tid; u2 < 1024; u2 += 256) {
            int n = u2 >> 3, q = u2 & 7;
            int v = v0 + n; if (v >= VOCAB) v = VOCAB - 1;
            uint32_t dst = sB_u + (0 * BSTRIDE + n * LDB + q * 8) * 2;
            cp16(dst, reinterpret_cast<const char*>(g_Wb) + ((size_t)v * HDIM + q * 8) * 2);
        }
        cp_commit();
        if (tid < 128) {
            int v = v0 + tid;
            biasS[tid] = (v < VOCAB) ? bout[v] : -30.0f;
        }

        float acc[2][8][4];
        #pragma unroll
        for (int mt = 0; mt < 2; ++mt)
            #pragma unroll
            for (int nt = 0; nt < 8; ++nt)
                #pragma unroll
                for (int q = 0; q < 4; ++q) acc[mt][nt][q] = 0.f;

        for (int st = 0; st < NSTAGES; ++st) {
            if (st + 1 < NSTAGES) {
                int kc = (st + 1) * KSTAGE;
                int buf = (st + 1) & 1;
                for (int u2 = tid; u2 < 1024; u2 += 256) {
                    int n = u2 >> 3, q = u2 & 7;
                    int v = v0 + n; if (v >= VOCAB) v = VOCAB - 1;
                    uint32_t dst = sB_u + (buf * BSTRIDE + n * LDB + q * 8) * 2;
                    cp16(dst, reinterpret_cast<const char*>(g_Wb) + ((size_t)v * HDIM + kc + q * 8) * 2);
                }
                cp_commit();
                cp_wait<1>();
            } else {
                cp_wait<0>();
            }
            __syncthreads();

            int buf = st & 1;
            uint32_t bbase = sB_u + buf * BSTRIDE * 2;
            #pragma unroll
            for (int sub = 0; sub < KSTAGE / 16; ++sub) {
                int kA = st * KSTAGE + sub * 16;
                int kB = sub * 16;
                uint32_t a0[2], a1[2], a2[2], a3[2];
                #pragma unroll
                for (int mt = 0; mt < 2; ++mt) {
                    uint32_t addr = sA_u + (((a_row + mt * 16) * LDA) + kA + a_coloff) * 2;
                    ldsm4(a0[mt], a1[mt], a2[mt], a3[mt], addr);
                }
                #pragma unroll
                for (int pair = 0; pair < 4; ++pair) {
                    int n0 = wn * 64 + pair * 16;
                    uint32_t addr = bbase + ((n0 + b_rowoff) * LDB + kB + b_coloff) * 2;
                    uint32_t b0, b1, b2, b3;
                    ldsm4(b0, b1, b2, b3, addr);
                    #pragma unroll
                    for (int mt = 0; mt < 2; ++mt) {
                        mma16816(acc[mt][pair * 2 + 0], a0[mt], a1[mt], a2[mt], a3[mt], b0, b1);
                        mma16816(acc[mt][pair * 2 + 1], a0[mt], a1[mt], a2[mt], a3[mt], b2, b3);
                    }
                }
            }
            __syncthreads();
        }

        #pragma unroll
        for (int mt = 0; mt < 2; ++mt)
            #pragma unroll
            for (int half = 0; half < 2; ++half) {
                float s = 0.f;
                #pragma unroll
                for (int nt = 0; nt < 8; ++nt) {
                    int cb = wn * 64 + nt * 8 + 2 * tig;
                    s += __expf(acc[mt][nt][half * 2 + 0] + biasS[cb]);
                    s += __expf(acc[mt][nt][half * 2 + 1] + biasS[cb + 1]);
                }
                s_slot[mt * 2 + half] += s;
            }
        __syncthreads();
    }

    #pragma unroll
    for (int k2 = 0; k2 < 4; ++k2) {
        float s = s_slot[k2];
        s += __shfl_xor_sync(0xffffffffu, s, 1);
        s += __shfl_xor_sync(0xffffffffu, s, 2);
        s_slot[k2] = s;
    }
    if (tig == 0) {
        #pragma unroll
        for (int k2 = 0; k2 < 4; ++k2) {
            int row = wm * 32 + (k2 >> 1) * 16 + (k2 & 1) * 8 + g;
            s_red[row * 2 + wn] = s_slot[k2];
        }
    }
    __syncthreads();

    float contrib = 0.f;
    if (tid < 128) {
        float st = s_red[tid * 2] + s_red[tid * 2 + 1];
        int i2 = i0 + tid;
        if (i2 < NT) {
            int n = i2 / TT, t = i2 - n * TT;
            int tg = captions[n * TFULL + t + 1];
            if (tg != 0) contrib = logf(st);
        }
    }
    #pragma unroll
    for (int off = 16; off; off >>= 1)
        contrib += __shfl_xor_sync(0xffffffffu, contrib, off);
    if (lane == 0) warp_sum[w] = contrib;
    __syncthreads();
    if (tid == 0) {
        float b = 0.f;
        #pragma unroll
        for (int q = 0; q < 8; ++q) b += warp_sum[q];
        atomicAdd(out, b * (1.0f / (float)NB));
    }
}

// ---------------- kernel 5: picked target scores ----------------
__global__ void __launch_bounds__(256) picked_kernel(const float* __restrict__ bout,
                                                     const int* __restrict__ captions,
                                                     float* __restrict__ out) {
    __shared__ float wsum[8];
    int lane = threadIdx.x & 31, w = threadIdx.x >> 5;
    int row = blockIdx.x * 8 + w;
    float c = 0.f;
    if (row < NT) {
        int n = row / TT, t = row - n * TT;
        int tg = captions[n * TFULL + t + 1];
        if (tg != 0) {
            const __nv_bfloat162* h2 = reinterpret_cast<const __nv_bfloat162*>(g_hsb + (size_t)row * HDIM);
            const __nv_bfloat162* w2 = reinterpret_cast<const __nv_bfloat162*>(g_Wb + (size_t)tg * HDIM);
            float acc = 0.f;
            #pragma unroll
            for (int q = 0; q < 8; ++q) {
                __nv_bfloat162 a = h2[lane + q * 32];
                __nv_bfloat162 b = w2[lane + q * 32];
                acc = fmaf(__bfloat162float(a.x), __bfloat162float(b.x), acc);
                acc = fmaf(__bfloat162float(a.y), __bfloat162float(b.y), acc);
            }
            #pragma unroll
            for (int off = 16; off; off >>= 1)
                acc += __shfl_xor_sync(0xffffffffu, acc, off);
            if (lane == 0) c = -(acc + bout[tg]) * (1.0f / (float)NB);
        }
    }
    if (lane == 0) wsum[w] = c;
    __syncthreads();
    if (threadIdx.x == 0) {
        float b = 0.f;
        #pragma unroll
        for (int q = 0; q < 8; ++q) b += wsum[q];
        if (b != 0.f) atomicAdd(out, b);
    }
}

// ---------------- launch ----------------
// rnn_kernel kept 4th so ncu's fixed skip-count lands on it again.
extern "C" void kernel_launch(void* const* d_in, const int* in_sizes, int n_in,
                              void* d_out, int out_size) {
    const float* feat   = (const float*)d_in[0];
    const float* W_proj = (const float*)d_in[1];
    const float* b_proj = (const float*)d_in[2];
    const float* W_emb  = (const float*)d_in[3];
    const float* Wx     = (const float*)d_in[4];
    const float* Wh     = (const float*)d_in[5];
    const float* b      = (const float*)d_in[6];
    const float* W_out  = (const float*)d_in[7];
    const float* b_out  = (const float*)d_in[8];
    const int*   caps   = (const int*)d_in[9];
    float* out = (float*)d_out;

    cudaFuncSetAttribute(loss_kernel, cudaFuncAttributeMaxDynamicSharedMemorySize, DSMEM);

    init_kernel<<<1, 32>>>(out);
    h0_kernel<<<dim3(4, 8), 256>>>(feat, W_proj, b_proj);
    xw_kernel<<<dim3(255, 4), 256>>>(caps, W_emb, Wx, b);
    rnn_kernel<<<128, 512>>>(Wh);
    wtrans_kernel<<<dim3(313, 16), 256>>>(W_out);
    loss_kernel<<<128, 256, DSMEM>>>(b_out, caps, out);
    picked_kernel<<<2040, 256>>>(b_out, caps, out);
}

// round 16
// speedup vs baseline: 1.1871x; 1.1871x over previous
#include <cuda_runtime.h>
#include <cuda_bf16.h>
#include <math.h>
#include <stdint.h>

#define NB    64
#define TFULL 256
#define TT    255
#define NT    (NB * TT)        // 16320 token rows
#define VOCAB 10000
#define DFEAT 1280
#define WDIM  256
#define HDIM  512

// ---- loss kernel tiling (HMMA mma.sync; KSTAGE=128) ----
#define LDA      520                 // bf16 elems per A smem row (512 + 8 pad)
#define LDB      136                 // bf16 elems per B smem row (128 + 8 pad)
#define KSTAGE   128
#define NSTAGES  (HDIM / KSTAGE)     // 4
#define BSTRIDE  (128 * LDB)         // bf16 elems per B stage
#define NVT      ((VOCAB + 127) / 128)   // 79 vocab tiles
#define DSMEM    (128 * LDA * 2 + 2 * 128 * LDB * 2)   // 133120 + 69632 = 202752

// ---- xw kernel tiling ----
#define XLD      264                 // bf16 elems per smem row (256 + 8 pad)
#define XW_SMEM  (2 * 128 * XLD * 2) // sA + sB = 135168

// ---------------- scratch (static device globals; no allocations) ----------------
__device__ float g_h[2][NB * HDIM];                       // ping-pong hidden state
__device__ float g_xW[NT * HDIM];                         // emb @ Wx + b
__device__ __align__(256) __nv_bfloat16 g_hsb[NT * HDIM]; // hidden states, bf16
__device__ __align__(256) __nv_bfloat16 g_Wb[VOCAB * HDIM];  // W_out^T bf16 [v][k]
__device__ __align__(256) __nv_bfloat16 g_Wxb[HDIM * WDIM];  // Wx^T bf16 [n][k] (512 x 256)
__device__ unsigned int g_rg_count[8 * 32];   // per-rowgroup barrier counters (128B apart)
__device__ unsigned int g_rg_gen[8 * 32];

extern __shared__ char dsm[];

// ---------------- asm helpers ----------------
__device__ __forceinline__ void cp16(uint32_t dst, const void* src) {
    asm volatile("cp.async.cg.shared.global [%0], [%1], 16;" :: "r"(dst), "l"(src));
}
__device__ __forceinline__ void cp_commit() { asm volatile("cp.async.commit_group;"); }
template <int N>
__device__ __forceinline__ void cp_wait() { asm volatile("cp.async.wait_group %0;" :: "n"(N)); }

__device__ __forceinline__ void ldsm4(uint32_t& r0, uint32_t& r1, uint32_t& r2, uint32_t& r3,
                                      uint32_t addr) {
    asm volatile("ldmatrix.sync.aligned.m8n8.x4.shared.b16 {%0,%1,%2,%3}, [%4];"
                 : "=r"(r0), "=r"(r1), "=r"(r2), "=r"(r3) : "r"(addr));
}
__device__ __forceinline__ void mma16816(float* c,
                                         uint32_t a0, uint32_t a1, uint32_t a2, uint32_t a3,
                                         uint32_t b0, uint32_t b1) {
    asm volatile("mma.sync.aligned.m16n8k16.row.col.f32.bf16.bf16.f32 "
                 "{%0,%1,%2,%3}, {%4,%5,%6,%7}, {%8,%9}, {%0,%1,%2,%3};"
                 : "+f"(c[0]), "+f"(c[1]), "+f"(c[2]), "+f"(c[3])
                 : "r"(a0), "r"(a1), "r"(a2), "r"(a3), "r"(b0), "r"(b1));
}
#define FFMA2(acc, a, b) \
    asm("fma.rn.f32x2 %0, %1, %2, %0;" : "+l"(acc) : "l"(a), "l"(b))

// ---------------- init ----------------
__global__ void init_kernel(float* out) {
    int tid = threadIdx.x;
    if (tid == 0) out[0] = 0.0f;
    if (tid < 8 * 32) { g_rg_count[tid] = 0u; g_rg_gen[tid] = 0u; }
}

// ---------------- kernel 1: h0 = feat @ W_proj + b_proj (fp32, exact) ----------------
__global__ void __launch_bounds__(256) h0_kernel(const float* __restrict__ feat,
                                                 const float* __restrict__ Wp,
                                                 const float* __restrict__ bp) {
    __shared__ float As[32][20];
    __shared__ float Bs[32][68];
    int tid = threadIdx.x;
    int r0 = blockIdx.x * 16;
    int c0 = blockIdx.y * 64;
    int r = tid >> 4;
    int cg = tid & 15;
    float acc0 = 0.f, acc1 = 0.f, acc2 = 0.f, acc3 = 0.f;

    for (int kc = 0; kc < DFEAT; kc += 32) {
        __syncthreads();
        if (tid < 128) {
            int row = tid >> 3, kq = (tid & 7) << 2;
            float4 v = *reinterpret_cast<const float4*>(feat + (size_t)(r0 + row) * DFEAT + kc + kq);
            As[kq + 0][row] = v.x; As[kq + 1][row] = v.y;
            As[kq + 2][row] = v.z; As[kq + 3][row] = v.w;
        }
        for (int u = tid; u < 512; u += 256) {
            int k = u >> 4, jq = (u & 15) << 2;
            *reinterpret_cast<float4*>(&Bs[k][jq]) =
                *reinterpret_cast<const float4*>(Wp + (size_t)(kc + k) * HDIM + c0 + jq);
        }
        __syncthreads();
        #pragma unroll
        for (int k = 0; k < 32; k++) {
            float a = As[k][r];
            float4 bv = *reinterpret_cast<const float4*>(&Bs[k][cg << 2]);
            acc0 = fmaf(a, bv.x, acc0); acc1 = fmaf(a, bv.y, acc1);
            acc2 = fmaf(a, bv.z, acc2); acc3 = fmaf(a, bv.w, acc3);
        }
    }
    int col = c0 + (cg << 2);
    float4 bb = *reinterpret_cast<const float4*>(bp + col);
    float4 o;
    o.x = acc0 + bb.x; o.y = acc1 + bb.y; o.z = acc2 + bb.z; o.w = acc3 + bb.w;
    *reinterpret_cast<float4*>(&g_h[0][(r0 + r) * HDIM + col]) = o;
}

// ---------------- kernel 2: wtrans = W_out -> g_Wb bf16 [v][k]  AND  Wx -> g_Wxb bf16 [n][k] ----------------
__global__ void __launch_bounds__(256) wtrans_kernel(const float* __restrict__ Wout,
                                                     const float* __restrict__ Wx) {
    __shared__ float tile[32][33];
    int tx = threadIdx.x & 31, ty = threadIdx.x >> 5;
    if (blockIdx.y < 16) {
        int v0 = blockIdx.x * 32, k0 = blockIdx.y * 32;
        for (int r = ty; r < 32; r += 8) {
            int vv = v0 + tx;
            tile[r][tx] = (vv < VOCAB) ? Wout[(size_t)(k0 + r) * VOCAB + vv] : 0.f;
        }
        __syncthreads();
        for (int r = ty; r < 32; r += 8) {
            int vv = v0 + r;
            if (vv < VOCAB)
                g_Wb[(size_t)vv * HDIM + k0 + tx] = __float2bfloat16(tile[tx][r]);
        }
    } else {
        // Wx transpose: Wx[k=256][n=512] -> g_Wxb[n][k] bf16. 128 tiles of 32x32.
        if (blockIdx.x >= 128) return;
        int k0 = (blockIdx.x & 7) * 32;
        int n0 = (blockIdx.x >> 3) * 32;
        for (int r = ty; r < 32; r += 8)
            tile[r][tx] = Wx[(size_t)(k0 + r) * HDIM + n0 + tx];
        __syncthreads();
        for (int r = ty; r < 32; r += 8)
            g_Wxb[(size_t)(n0 + r) * WDIM + k0 + tx] = __float2bfloat16(tile[tx][r]);
    }
}

// ---------------- kernel 3: xw = gather(W_embed) @ Wx + b  (bf16 HMMA) ----------------
// grid (128, 4): 128-row x 128-col tiles; K = 256, fully smem-resident (no staging).
__global__ void __launch_bounds__(256, 1) xw_kernel(const int* __restrict__ captions,
                                                    const float* __restrict__ Wemb,
                                                    const float* __restrict__ bias) {
    __nv_bfloat16* sA = reinterpret_cast<__nv_bfloat16*>(dsm);                 // 128 x XLD
    __nv_bfloat16* sB = reinterpret_cast<__nv_bfloat16*>(dsm + 128 * XLD * 2); // 128 x XLD
    __shared__ const float* Arow[128];
    __shared__ float biasS[128];

    int tid = threadIdx.x;
    int lane = tid & 31, w = tid >> 5;
    int wm = w >> 1, wn = w & 1;
    int g = lane >> 2, tig = lane & 3;
    int i0 = blockIdx.x * 128;
    int c0 = blockIdx.y * 128;

    if (tid < 128) {
        int i = i0 + tid; if (i >= NT) i = NT - 1;
        int n = i / TT;
        int t = i - n * TT;
        Arow[tid] = Wemb + (size_t)captions[n * TFULL + t] * WDIM;
        biasS[tid] = bias[c0 + tid];
    }

    uint32_t sA_u = (uint32_t)__cvta_generic_to_shared(sA);
    uint32_t sB_u = (uint32_t)__cvta_generic_to_shared(sB);

    // B: 128 n-rows x 256 k bf16 via cp.async from pre-transposed g_Wxb
    for (int u = tid; u < 4096; u += 256) {
        int nrow = u >> 5, q = u & 31;
        cp16(sB_u + (uint32_t)(nrow * XLD + q * 8) * 2,
             reinterpret_cast<const char*>(g_Wxb) + ((size_t)(c0 + nrow) * WDIM + q * 8) * 2);
    }
    cp_commit();
    __syncthreads();   // Arow visible

    // A: gather 128 token rows, convert fp32 -> bf16 inline
    for (int u = tid; u < 8192; u += 256) {
        int row = u >> 6, q = u & 63;
        float4 v = *reinterpret_cast<const float4*>(Arow[row] + q * 4);
        __nv_bfloat162 p0 = __floats2bfloat162_rn(v.x, v.y);
        __nv_bfloat162 p1 = __floats2bfloat162_rn(v.z, v.w);
        char* dst = reinterpret_cast<char*>(sA) + row * (XLD * 2) + q * 8;
        *reinterpret_cast<__nv_bfloat162*>(dst) = p0;
        *reinterpret_cast<__nv_bfloat162*>(dst + 4) = p1;
    }
    cp_wait<0>();
    __syncthreads();

    int j = lane >> 3, i8 = lane & 7;
    int a_row    = wm * 32 + (j & 1) * 8 + i8;
    int a_coloff = (j >> 1) * 8;
    int b_rowoff = (j >> 1) * 8 + i8;
    int b_coloff = (j & 1) * 8;

    float acc[2][8][4];
    #pragma unroll
    for (int mt = 0; mt < 2; ++mt)
        #pragma unroll
        for (int nt = 0; nt < 8; ++nt)
            #pragma unroll
            for (int q = 0; q < 4; ++q) acc[mt][nt][q] = 0.f;

    #pragma unroll
    for (int sub = 0; sub < 16; ++sub) {
        int kA = sub * 16;
        uint32_t a0[2], a1[2], a2[2], a3[2];
        #pragma unroll
        for (int mt = 0; mt < 2; ++mt) {
            uint32_t addr = sA_u + (uint32_t)(((a_row + mt * 16) * XLD) + kA + a_coloff) * 2;
            ldsm4(a0[mt], a1[mt], a2[mt], a3[mt], addr);
        }
        #pragma unroll
        for (int pair = 0; pair < 4; ++pair) {
            int n0 = wn * 64 + pair * 16;
            uint32_t addr = sB_u + (uint32_t)(((n0 + b_rowoff) * XLD) + kA + b_coloff) * 2;
            uint32_t b0, b1, b2, b3;
            ldsm4(b0, b1, b2, b3, addr);
            #pragma unroll
            for (int mt = 0; mt < 2; ++mt) {
                mma16816(acc[mt][pair * 2 + 0], a0[mt], a1[mt], a2[mt], a3[mt], b0, b1);
                mma16816(acc[mt][pair * 2 + 1], a0[mt], a1[mt], a2[mt], a3[mt], b2, b3);
            }
        }
    }

    // epilogue: add bias, store fp32 (row-guarded)
    #pragma unroll
    for (int mt = 0; mt < 2; ++mt)
        #pragma unroll
        for (int nt = 0; nt < 8; ++nt) {
            int lc = wn * 64 + nt * 8 + tig * 2;
            int col = c0 + lc;
            float b0 = biasS[lc], b1 = biasS[lc + 1];
            int r0i = i0 + wm * 32 + mt * 16 + g;
            if (r0i < NT) {
                float2 o; o.x = acc[mt][nt][0] + b0; o.y = acc[mt][nt][1] + b1;
                *reinterpret_cast<float2*>(g_xW + (size_t)r0i * HDIM + col) = o;
            }
            if (r0i + 8 < NT) {
                float2 o; o.x = acc[mt][nt][2] + b0; o.y = acc[mt][nt][3] + b1;
                *reinterpret_cast<float2*>(g_xW + (size_t)(r0i + 8) * HDIM + col) = o;
            }
        }
}

// ---------------- per-rowgroup barrier: 16 blocks, release/acquire ----------------
__device__ __forceinline__ void rg_barrier(unsigned int rgoff, unsigned int want) {
    __syncthreads();
    if (threadIdx.x == 0) {
        unsigned int old;
        asm volatile("atom.add.release.gpu.global.u32 %0, [%1], 1;"
                     : "=r"(old) : "l"(g_rg_count + rgoff) : "memory");
        if (old == 15u) {
            g_rg_count[rgoff] = 0u;
            asm volatile("st.release.gpu.global.u32 [%0], %1;"
                         :: "l"(g_rg_gen + rgoff), "r"(want) : "memory");
        } else {
            unsigned int g;
            do {
                asm volatile("ld.acquire.gpu.global.u32 %0, [%1];"
                             : "=r"(g) : "l"(g_rg_gen + rgoff) : "memory");
            } while (g < want);
        }
    }
    __syncthreads();
}

// ---------------- kernel 4: RNN scan (R9 proven version) ----------------
__global__ void __launch_bounds__(256, 1) rnn_kernel(const float* __restrict__ Wh) {
    __shared__ __align__(16) float hsm[8 * 512];   // 16 KB, contiguous TMA dest
    __shared__ float part[8 * 8 * 32];             // [row][ks][lane] 8 KB
    __shared__ __align__(8) unsigned long long mbar;
    int tid = threadIdx.x;
    int cg = blockIdx.x & 15, rg = blockIdx.x >> 4;
    int c0 = cg << 5, r0 = rg << 3;
    int lane = tid & 31, wid = tid >> 5;
    int gcol = c0 + lane;
    unsigned int rgoff = (unsigned)rg * 32u;

    unsigned long long wreg[32];
    #pragma unroll
    for (int j2 = 0; j2 < 32; ++j2) {
        int k = wid * 64 + j2 * 2;
        float lo = Wh[(size_t)k * HDIM + gcol];
        float hi = Wh[(size_t)(k + 1) * HDIM + gcol];
        asm("mov.b64 %0, {%1, %2};" : "=l"(wreg[j2]) : "f"(lo), "f"(hi));
    }

    uint32_t hsm_u = (uint32_t)__cvta_generic_to_shared(hsm);
    uint32_t mbar_u = (uint32_t)__cvta_generic_to_shared(&mbar);
    if (tid == 0) {
        asm volatile("mbarrier.init.shared.b64 [%0], 1;" :: "r"(mbar_u) : "memory");
        asm volatile("fence.proxy.async;" ::: "memory");
    }
    __syncthreads();

    for (int t = 0; t < TT; t++) {
        if (tid == 0) {
            asm volatile("mbarrier.arrive.expect_tx.shared.b64 _, [%0], %1;"
                         :: "r"(mbar_u), "r"(16384u) : "memory");
            asm volatile("cp.async.bulk.shared::cta.global.mbarrier::complete_tx::bytes "
                         "[%0], [%1], %2, [%3];"
                         :: "r"(hsm_u), "l"(g_h[t & 1] + (size_t)r0 * HDIM),
                            "r"(16384u), "r"(mbar_u) : "memory");
        }
        float xw = g_xW[((size_t)(r0 + wid) * TT + t) * HDIM + gcol];
        {
            unsigned int ph = (unsigned)(t & 1);
            asm volatile(
                "{\n\t.reg .pred P;\n\t"
                "W_%=:\n\t"
                "mbarrier.try_wait.parity.acquire.cta.shared::cta.b64 P, [%0], %1, 0x989680;\n\t"
                "@P bra D_%=;\n\t"
                "bra W_%=;\n\t"
                "D_%=:\n\t}"
                :: "r"(mbar_u), "r"(ph) : "memory");
        }

        #pragma unroll
        for (int r = 0; r < 8; ++r) {
            const ulonglong2* hp = reinterpret_cast<const ulonglong2*>(hsm + r * 512 + wid * 64);
            unsigned long long a0 = 0ull, a1 = 0ull, a2 = 0ull, a3 = 0ull;
            #pragma unroll
            for (int jj = 0; jj < 16; jj += 2) {
                ulonglong2 v0 = hp[jj];
                ulonglong2 v1 = hp[jj + 1];
                FFMA2(a0, v0.x, wreg[2 * jj + 0]);
                FFMA2(a1, v0.y, wreg[2 * jj + 1]);
                FFMA2(a2, v1.x, wreg[2 * jj + 2]);
                FFMA2(a3, v1.y, wreg[2 * jj + 3]);
            }
            unsigned long long s01, s23, s;
            asm("add.rn.f32x2 %0, %1, %2;" : "=l"(s01) : "l"(a0), "l"(a1));
            asm("add.rn.f32x2 %0, %1, %2;" : "=l"(s23) : "l"(a2), "l"(a3));
            asm("add.rn.f32x2 %0, %1, %2;" : "=l"(s)   : "l"(s01), "l"(s23));
            float lo, hi;
            asm("mov.b64 {%0, %1}, %2;" : "=f"(lo), "=f"(hi) : "l"(s));
            part[(r * 8 + wid) * 32 + lane] = lo + hi;
        }
        __syncthreads();

        float acc = 0.f;
        #pragma unroll
        for (int ks = 0; ks < 8; ++ks) acc += part[(wid * 8 + ks) * 32 + lane];
        float hn = tanhf(acc + xw);
        __stcg(&g_h[(t + 1) & 1][(size_t)(r0 + wid) * HDIM + gcol], hn);
        g_hsb[((size_t)(r0 + wid) * TT + t) * HDIM + gcol] = __float2bfloat16(hn);

        rg_barrier(rgoff, (unsigned)(t + 1));
    }
}

// ---------------- kernel 5: bf16 HMMA scores GEMM + exp-sum epilogue (KSTAGE=128) ----------------
__global__ void __launch_bounds__(256, 1) loss_kernel(const float* __restrict__ bout,
                                                      const int* __restrict__ captions,
                                                      float* __restrict__ out) {
    __nv_bfloat16* sA = reinterpret_cast<__nv_bfloat16*>(dsm);               // 128 x LDA
    __nv_bfloat16* sB = reinterpret_cast<__nv_bfloat16*>(dsm + 128 * LDA * 2); // 2 x 128 x LDB
    __shared__ float biasS[128];
    __shared__ float s_red[256];
    __shared__ float warp_sum[8];

    int tid = threadIdx.x;
    int lane = tid & 31, w = tid >> 5;
    int wm = w >> 1, wn = w & 1;
    int g = lane >> 2, tig = lane & 3;
    int i0 = blockIdx.x * 128;

    const char* hsb_base = reinterpret_cast<const char*>(g_hsb);
    for (int u = tid; u < 8192; u += 256) {
        int r = u >> 6, q = u & 63;
        int gi = i0 + r; if (gi >= NT) gi = NT - 1;
        float4 v = *reinterpret_cast<const float4*>(hsb_base + ((size_t)gi * HDIM + q * 8) * 2);
        *reinterpret_cast<float4*>(reinterpret_cast<char*>(sA) + (size_t)r * LDA * 2 + q * 16) = v;
    }
    __syncthreads();

    uint32_t sA_u = (uint32_t)__cvta_generic_to_shared(sA);
    uint32_t sB_u = (uint32_t)__cvta_generic_to_shared(sB);

    int j = lane >> 3, i8 = lane & 7;
    int a_row    = wm * 32 + (j & 1) * 8 + i8;
    int a_coloff = (j >> 1) * 8;
    int b_rowoff = (j >> 1) * 8 + i8;
    int b_coloff = (j & 1) * 8;

    float s_slot[4] = {0.f, 0.f, 0.f, 0.f};

    for (int vt = 0; vt < NVT; ++vt) {
        int v0 = vt * 128;
        // preload B stage 0 (128 vocab rows x 128 k = 32KB)
        for (int u2 = tid; u2 < 2048; u2 += 256) {
            int n = u2 >> 4, q = u2 & 15;
            int v = v0 + n; if (v >= VOCAB) v = VOCAB - 1;
            uint32_t dst = sB_u + (uint32_t)(0 * BSTRIDE + n * LDB + q * 8) * 2;
            cp16(dst, reinterpret_cast<const char*>(g_Wb) + ((size_t)v * HDIM + q * 8) * 2);
        }
        cp_commit();
        if (tid < 128) {
            int v = v0 + tid;
            biasS[tid] = (v < VOCAB) ? bout[v] : -30.0f;
        }

        float acc[2][8][4];
        #pragma unroll
        for (int mt = 0; mt < 2; ++mt)
            #pragma unroll
            for (int nt = 0; nt < 8; ++nt)
                #pragma unroll
                for (int q = 0; q < 4; ++q) acc[mt][nt][q] = 0.f;

        for (int st = 0; st < NSTAGES; ++st) {
            if (st + 1 < NSTAGES) {
                int kc = (st + 1) * KSTAGE;
                int buf = (st + 1) & 1;
                for (int u2 = tid; u2 < 2048; u2 += 256) {
                    int n = u2 >> 4, q = u2 & 15;
                    int v = v0 + n; if (v >= VOCAB) v = VOCAB - 1;
                    uint32_t dst = sB_u + (uint32_t)(buf * BSTRIDE + n * LDB + q * 8) * 2;
                    cp16(dst, reinterpret_cast<const char*>(g_Wb) + ((size_t)v * HDIM + kc + q * 8) * 2);
                }
                cp_commit();
                cp_wait<1>();
            } else {
                cp_wait<0>();
            }
            __syncthreads();

            int buf = st & 1;
            uint32_t bbase = sB_u + (uint32_t)buf * BSTRIDE * 2;
            #pragma unroll
            for (int sub = 0; sub < KSTAGE / 16; ++sub) {
                int kA = st * KSTAGE + sub * 16;
                int kB = sub * 16;
                uint32_t a0[2], a1[2], a2[2], a3[2];
                #pragma unroll
                for (int mt = 0; mt < 2; ++mt) {
                    uint32_t addr = sA_u + (uint32_t)(((a_row + mt * 16) * LDA) + kA + a_coloff) * 2;
                    ldsm4(a0[mt], a1[mt], a2[mt], a3[mt], addr);
                }
                #pragma unroll
                for (int pair = 0; pair < 4; ++pair) {
                    int n0 = wn * 64 + pair * 16;
                    uint32_t addr = bbase + (uint32_t)(((n0 + b_rowoff) * LDB) + kB + b_coloff) * 2;
                    uint32_t b0, b1, b2, b3;
                    ldsm4(b0, b1, b2, b3, addr);
                    #pragma unroll
                    for (int mt = 0; mt < 2; ++mt) {
                        mma16816(acc[mt][pair * 2 + 0], a0[mt], a1[mt], a2[mt], a3[mt], b0, b1);
                        mma16816(acc[mt][pair * 2 + 1], a0[mt], a1[mt], a2[mt], a3[mt], b2, b3);
                    }
                }
            }
            __syncthreads();
        }

        #pragma unroll
        for (int mt = 0; mt < 2; ++mt)
            #pragma unroll
            for (int half = 0; half < 2; ++half) {
                float s = 0.f;
                #pragma unroll
                for (int nt = 0; nt < 8; ++nt) {
                    int cb = wn * 64 + nt * 8 + 2 * tig;
                    s += __expf(acc[mt][nt][half * 2 + 0] + biasS[cb]);
                    s += __expf(acc[mt][nt][half * 2 + 1] + biasS[cb + 1]);
                }
                s_slot[mt * 2 + half] += s;
            }
        __syncthreads();
    }

    #pragma unroll
    for (int k2 = 0; k2 < 4; ++k2) {
        float s = s_slot[k2];
        s += __shfl_xor_sync(0xffffffffu, s, 1);
        s += __shfl_xor_sync(0xffffffffu, s, 2);
        s_slot[k2] = s;
    }
    if (tig == 0) {
        #pragma unroll
        for (int k2 = 0; k2 < 4; ++k2) {
            int row = wm * 32 + (k2 >> 1) * 16 + (k2 & 1) * 8 + g;
            s_red[row * 2 + wn] = s_slot[k2];
        }
    }
    __syncthreads();

    float contrib = 0.f;
    if (tid < 128) {
        float st = s_red[tid * 2] + s_red[tid * 2 + 1];
        int i2 = i0 + tid;
        if (i2 < NT) {
            int n = i2 / TT, t = i2 - n * TT;
            int tg = captions[n * TFULL + t + 1];
            if (tg != 0) contrib = logf(st);
        }
    }
    #pragma unroll
    for (int off = 16; off; off >>= 1)
        contrib += __shfl_xor_sync(0xffffffffu, contrib, off);
    if (lane == 0) warp_sum[w] = contrib;
    __syncthreads();
    if (tid == 0) {
        float b = 0.f;
        #pragma unroll
        for (int q = 0; q < 8; ++q) b += warp_sum[q];
        atomicAdd(out, b * (1.0f / (float)NB));
    }
}

// ---------------- kernel 6: picked target scores ----------------
__global__ void __launch_bounds__(256) picked_kernel(const float* __restrict__ bout,
                                                     const int* __restrict__ captions,
                                                     float* __restrict__ out) {
    __shared__ float wsum[8];
    int lane = threadIdx.x & 31, w = threadIdx.x >> 5;
    int row = blockIdx.x * 8 + w;
    float c = 0.f;
    if (row < NT) {
        int n = row / TT, t = row - n * TT;
        int tg = captions[n * TFULL + t + 1];
        if (tg != 0) {
            const __nv_bfloat162* h2 = reinterpret_cast<const __nv_bfloat162*>(g_hsb + (size_t)row * HDIM);
            const __nv_bfloat162* w2 = reinterpret_cast<const __nv_bfloat162*>(g_Wb + (size_t)tg * HDIM);
            float acc = 0.f;
            #pragma unroll
            for (int q = 0; q < 8; ++q) {
                __nv_bfloat162 a = h2[lane + q * 32];
                __nv_bfloat162 b = w2[lane + q * 32];
                acc = fmaf(__bfloat162float(a.x), __bfloat162float(b.x), acc);
                acc = fmaf(__bfloat162float(a.y), __bfloat162float(b.y), acc);
            }
            #pragma unroll
            for (int off = 16; off; off >>= 1)
                acc += __shfl_xor_sync(0xffffffffu, acc, off);
            if (lane == 0) c = -(acc + bout[tg]) * (1.0f / (float)NB);
        }
    }
    if (lane == 0) wsum[w] = c;
    __syncthreads();
    if (threadIdx.x == 0) {
        float b = 0.f;
        #pragma unroll
        for (int q = 0; q < 8; ++q) b += wsum[q];
        if (b != 0.f) atomicAdd(out, b);
    }
}

// ---------------- launch ----------------
// Order: init(1) h0(2) wtrans(3) xw(4) rnn(5) loss(6) picked(7) → ncu -s 5 -c 1 lands on loss.
extern "C" void kernel_launch(void* const* d_in, const int* in_sizes, int n_in,
                              void* d_out, int out_size) {
    const float* feat   = (const float*)d_in[0];
    const float* W_proj = (const float*)d_in[1];
    const float* b_proj = (const float*)d_in[2];
    const float* W_emb  = (const float*)d_in[3];
    const float* Wx     = (const float*)d_in[4];
    const float* Wh     = (const float*)d_in[5];
    const float* b      = (const float*)d_in[6];
    const float* W_out  = (const float*)d_in[7];
    const float* b_out  = (const float*)d_in[8];
    const int*   caps   = (const int*)d_in[9];
    float* out = (float*)d_out;

    cudaFuncSetAttribute(loss_kernel, cudaFuncAttributeMaxDynamicSharedMemorySize, DSMEM);
    cudaFuncSetAttribute(xw_kernel,   cudaFuncAttributeMaxDynamicSharedMemorySize, XW_SMEM);

    init_kernel<<<1, 256>>>(out);
    h0_kernel<<<dim3(4, 8), 256>>>(feat, W_proj, b_proj);
    wtrans_kernel<<<dim3(313, 17), 256>>>(W_out, Wx);
    xw_kernel<<<dim3(128, 4), 256, XW_SMEM>>>(caps, W_emb, b);
    rnn_kernel<<<128, 256>>>(Wh);
    loss_kernel<<<128, 256, DSMEM>>>(b_out, caps, out);
    picked_kernel<<<2040, 256>>>(b_out, caps, out);
}

// round 17
// speedup vs baseline: 1.2761x; 1.0750x over previous
#include <cuda_runtime.h>
#include <cuda_bf16.h>
#include <math.h>
#include <stdint.h>

#define NB    64
#define TFULL 256
#define TT    255
#define NT    (NB * TT)        // 16320 token rows
#define VOCAB 10000
#define DFEAT 1280
#define WDIM  256
#define HDIM  512

// ---- loss kernel tiling (HMMA mma.sync; KSTAGE=128) ----
#define LDA      520
#define LDB      136
#define KSTAGE   128
#define NSTAGES  (HDIM / KSTAGE)     // 4
#define BSTRIDE  (128 * LDB)
#define NVT      ((VOCAB + 127) / 128)   // 79
#define DSMEM    (128 * LDA * 2 + 2 * 128 * LDB * 2)   // 202752

// ---- xw kernel tiling ----
#define XLD      264
#define XW_SMEM  (2 * 128 * XLD * 2)

// ---- rnn: 8 rowgroups x 8 colgroups; cluster of 8 CTAs = one rowgroup ----
// dsm layout: hsm[2][8cg][8row][64] (32KB) + part[4096] (16KB) + stage[512] (2KB)
#define RNN_SMEM   51200
#define HSM_FLOATS 8192          // 2*8*8*64
#define PART_OFF   32768
#define STAGE_OFF  49152

// ---------------- scratch (static device globals; no allocations) ----------------
__device__ float g_h[2][NB * HDIM];                       // [0] = h0 input
__device__ float g_xW[NT * HDIM];
__device__ __align__(256) __nv_bfloat16 g_hsb[NT * HDIM];
__device__ __align__(256) __nv_bfloat16 g_Wb[VOCAB * HDIM];
__device__ __align__(256) __nv_bfloat16 g_Wxb[HDIM * WDIM];

extern __shared__ char dsm[];

// ---------------- asm helpers ----------------
__device__ __forceinline__ void cp16(uint32_t dst, const void* src) {
    asm volatile("cp.async.cg.shared.global [%0], [%1], 16;" :: "r"(dst), "l"(src));
}
__device__ __forceinline__ void cp_commit() { asm volatile("cp.async.commit_group;"); }
template <int N>
__device__ __forceinline__ void cp_wait() { asm volatile("cp.async.wait_group %0;" :: "n"(N)); }

__device__ __forceinline__ void ldsm4(uint32_t& r0, uint32_t& r1, uint32_t& r2, uint32_t& r3,
                                      uint32_t addr) {
    asm volatile("ldmatrix.sync.aligned.m8n8.x4.shared.b16 {%0,%1,%2,%3}, [%4];"
                 : "=r"(r0), "=r"(r1), "=r"(r2), "=r"(r3) : "r"(addr));
}
__device__ __forceinline__ void mma16816(float* c,
                                         uint32_t a0, uint32_t a1, uint32_t a2, uint32_t a3,
                                         uint32_t b0, uint32_t b1) {
    asm volatile("mma.sync.aligned.m16n8k16.row.col.f32.bf16.bf16.f32 "
                 "{%0,%1,%2,%3}, {%4,%5,%6,%7}, {%8,%9}, {%0,%1,%2,%3};"
                 : "+f"(c[0]), "+f"(c[1]), "+f"(c[2]), "+f"(c[3])
                 : "r"(a0), "r"(a1), "r"(a2), "r"(a3), "r"(b0), "r"(b1));
}
#define FFMA2(acc, a, b) \
    asm("fma.rn.f32x2 %0, %1, %2, %0;" : "+l"(acc) : "l"(a), "l"(b))

#define MBARRIER_INIT(addr, cnt) \
    asm volatile("mbarrier.init.shared.b64 [%0], %1;" :: "r"(addr), "r"((uint32_t)(cnt)) : "memory")
#define MBARRIER_EXPECT_TX(addr, bytes) \
    asm volatile("mbarrier.arrive.expect_tx.shared.b64 _, [%0], %1;" :: "r"(addr), "r"((uint32_t)(bytes)) : "memory")
#define MBARRIER_ARRIVE_LOCAL(addr) \
    asm volatile("mbarrier.arrive.shared.b64 _, [%0];" :: "r"(addr) : "memory")
#define MBARRIER_ARRIVE_REMOTE(addr) \
    asm volatile("mbarrier.arrive.shared::cluster.b64 _, [%0];" :: "r"(addr) : "memory")

__device__ __forceinline__ void wait_parity(uint32_t mbar_u, uint32_t ph) {
    asm volatile(
        "{\n\t.reg .pred P;\n\t"
        "W_%=:\n\t"
        "mbarrier.try_wait.parity.acquire.cta.shared::cta.b64 P, [%0], %1, 0x989680;\n\t"
        "@P bra D_%=;\n\t"
        "bra W_%=;\n\t"
        "D_%=:\n\t}"
        :: "r"(mbar_u), "r"(ph) : "memory");
}

__device__ __forceinline__ uint32_t mapa_u32(uint32_t addr, uint32_t rank) {
    uint32_t r;
    asm("mapa.shared::cluster.u32 %0, %1, %2;" : "=r"(r) : "r"(addr), "r"(rank));
    return r;
}

// ---------------- init ----------------
__global__ void init_kernel(float* out) {
    if (threadIdx.x == 0) out[0] = 0.0f;
}

// ---------------- kernel 1: h0 = feat @ W_proj + b_proj (fp32, exact) ----------------
__global__ void __launch_bounds__(256) h0_kernel(const float* __restrict__ feat,
                                                 const float* __restrict__ Wp,
                                                 const float* __restrict__ bp) {
    __shared__ float As[32][20];
    __shared__ float Bs[32][68];
    int tid = threadIdx.x;
    int r0 = blockIdx.x * 16;
    int c0 = blockIdx.y * 64;
    int r = tid >> 4;
    int cg = tid & 15;
    float acc0 = 0.f, acc1 = 0.f, acc2 = 0.f, acc3 = 0.f;

    for (int kc = 0; kc < DFEAT; kc += 32) {
        __syncthreads();
        if (tid < 128) {
            int row = tid >> 3, kq = (tid & 7) << 2;
            float4 v = *reinterpret_cast<const float4*>(feat + (size_t)(r0 + row) * DFEAT + kc + kq);
            As[kq + 0][row] = v.x; As[kq + 1][row] = v.y;
            As[kq + 2][row] = v.z; As[kq + 3][row] = v.w;
        }
        for (int u = tid; u < 512; u += 256) {
            int k = u >> 4, jq = (u & 15) << 2;
            *reinterpret_cast<float4*>(&Bs[k][jq]) =
                *reinterpret_cast<const float4*>(Wp + (size_t)(kc + k) * HDIM + c0 + jq);
        }
        __syncthreads();
        #pragma unroll
        for (int k = 0; k < 32; k++) {
            float a = As[k][r];
            float4 bv = *reinterpret_cast<const float4*>(&Bs[k][cg << 2]);
            acc0 = fmaf(a, bv.x, acc0); acc1 = fmaf(a, bv.y, acc1);
            acc2 = fmaf(a, bv.z, acc2); acc3 = fmaf(a, bv.w, acc3);
        }
    }
    int col = c0 + (cg << 2);
    float4 bb = *reinterpret_cast<const float4*>(bp + col);
    float4 o;
    o.x = acc0 + bb.x; o.y = acc1 + bb.y; o.z = acc2 + bb.z; o.w = acc3 + bb.w;
    *reinterpret_cast<float4*>(&g_h[0][(r0 + r) * HDIM + col]) = o;
}

// ---------------- kernel 2: wtrans ----------------
__global__ void __launch_bounds__(256) wtrans_kernel(const float* __restrict__ Wout,
                                                     const float* __restrict__ Wx) {
    __shared__ float tile[32][33];
    int tx = threadIdx.x & 31, ty = threadIdx.x >> 5;
    if (blockIdx.y < 16) {
        int v0 = blockIdx.x * 32, k0 = blockIdx.y * 32;
        for (int r = ty; r < 32; r += 8) {
            int vv = v0 + tx;
            tile[r][tx] = (vv < VOCAB) ? Wout[(size_t)(k0 + r) * VOCAB + vv] : 0.f;
        }
        __syncthreads();
        for (int r = ty; r < 32; r += 8) {
            int vv = v0 + r;
            if (vv < VOCAB)
                g_Wb[(size_t)vv * HDIM + k0 + tx] = __float2bfloat16(tile[tx][r]);
        }
    } else {
        if (blockIdx.x >= 128) return;
        int k0 = (blockIdx.x & 7) * 32;
        int n0 = (blockIdx.x >> 3) * 32;
        for (int r = ty; r < 32; r += 8)
            tile[r][tx] = Wx[(size_t)(k0 + r) * HDIM + n0 + tx];
        __syncthreads();
        for (int r = ty; r < 32; r += 8)
            g_Wxb[(size_t)(n0 + r) * WDIM + k0 + tx] = __float2bfloat16(tile[tx][r]);
    }
}

// ---------------- kernel 3: xw = gather(W_embed) @ Wx + b  (bf16 HMMA) ----------------
__global__ void __launch_bounds__(256, 1) xw_kernel(const int* __restrict__ captions,
                                                    const float* __restrict__ Wemb,
                                                    const float* __restrict__ bias) {
    __nv_bfloat16* sA = reinterpret_cast<__nv_bfloat16*>(dsm);
    __nv_bfloat16* sB = reinterpret_cast<__nv_bfloat16*>(dsm + 128 * XLD * 2);
    __shared__ const float* Arow[128];
    __shared__ float biasS[128];

    int tid = threadIdx.x;
    int lane = tid & 31, w = tid >> 5;
    int wm = w >> 1, wn = w & 1;
    int g = lane >> 2, tig = lane & 3;
    int i0 = blockIdx.x * 128;
    int c0 = blockIdx.y * 128;

    if (tid < 128) {
        int i = i0 + tid; if (i >= NT) i = NT - 1;
        int n = i / TT;
        int t = i - n * TT;
        Arow[tid] = Wemb + (size_t)captions[n * TFULL + t] * WDIM;
        biasS[tid] = bias[c0 + tid];
    }

    uint32_t sA_u = (uint32_t)__cvta_generic_to_shared(sA);
    uint32_t sB_u = (uint32_t)__cvta_generic_to_shared(sB);

    for (int u = tid; u < 4096; u += 256) {
        int nrow = u >> 5, q = u & 31;
        cp16(sB_u + (uint32_t)(nrow * XLD + q * 8) * 2,
             reinterpret_cast<const char*>(g_Wxb) + ((size_t)(c0 + nrow) * WDIM + q * 8) * 2);
    }
    cp_commit();
    __syncthreads();

    for (int u = tid; u < 8192; u += 256) {
        int row = u >> 6, q = u & 63;
        float4 v = *reinterpret_cast<const float4*>(Arow[row] + q * 4);
        __nv_bfloat162 p0 = __floats2bfloat162_rn(v.x, v.y);
        __nv_bfloat162 p1 = __floats2bfloat162_rn(v.z, v.w);
        char* dst = reinterpret_cast<char*>(sA) + row * (XLD * 2) + q * 8;
        *reinterpret_cast<__nv_bfloat162*>(dst) = p0;
        *reinterpret_cast<__nv_bfloat162*>(dst + 4) = p1;
    }
    cp_wait<0>();
    __syncthreads();

    int j = lane >> 3, i8 = lane & 7;
    int a_row    = wm * 32 + (j & 1) * 8 + i8;
    int a_coloff = (j >> 1) * 8;
    int b_rowoff = (j >> 1) * 8 + i8;
    int b_coloff = (j & 1) * 8;

    float acc[2][8][4];
    #pragma unroll
    for (int mt = 0; mt < 2; ++mt)
        #pragma unroll
        for (int nt = 0; nt < 8; ++nt)
            #pragma unroll
            for (int q = 0; q < 4; ++q) acc[mt][nt][q] = 0.f;

    #pragma unroll
    for (int sub = 0; sub < 16; ++sub) {
        int kA = sub * 16;
        uint32_t a0[2], a1[2], a2[2], a3[2];
        #pragma unroll
        for (int mt = 0; mt < 2; ++mt) {
            uint32_t addr = sA_u + (uint32_t)(((a_row + mt * 16) * XLD) + kA + a_coloff) * 2;
            ldsm4(a0[mt], a1[mt], a2[mt], a3[mt], addr);
        }
        #pragma unroll
        for (int pair = 0; pair < 4; ++pair) {
            int n0 = wn * 64 + pair * 16;
            uint32_t addr = sB_u + (uint32_t)(((n0 + b_rowoff) * XLD) + kA + b_coloff) * 2;
            uint32_t b0, b1, b2, b3;
            ldsm4(b0, b1, b2, b3, addr);
            #pragma unroll
            for (int mt = 0; mt < 2; ++mt) {
                mma16816(acc[mt][pair * 2 + 0], a0[mt], a1[mt], a2[mt], a3[mt], b0, b1);
                mma16816(acc[mt][pair * 2 + 1], a0[mt], a1[mt], a2[mt], a3[mt], b2, b3);
            }
        }
    }

    #pragma unroll
    for (int mt = 0; mt < 2; ++mt)
        #pragma unroll
        for (int nt = 0; nt < 8; ++nt) {
            int lc = wn * 64 + nt * 8 + tig * 2;
            int col = c0 + lc;
            float b0 = biasS[lc], b1 = biasS[lc + 1];
            int r0i = i0 + wm * 32 + mt * 16 + g;
            if (r0i < NT) {
                float2 o; o.x = acc[mt][nt][0] + b0; o.y = acc[mt][nt][1] + b1;
                *reinterpret_cast<float2*>(g_xW + (size_t)r0i * HDIM + col) = o;
            }
            if (r0i + 8 < NT) {
                float2 o; o.x = acc[mt][nt][2] + b0; o.y = acc[mt][nt][3] + b1;
                *reinterpret_cast<float2*>(g_xW + (size_t)(r0i + 8) * HDIM + col) = o;
            }
        }
}

// ---------------- kernel 4: RNN scan via 8-CTA clusters + DSMEM bulk exchange ----------------
// 64 CTAs x 512 threads; cluster = rowgroup (8 rows), CTA = 64 cols.
// h in smem only, layout hsm[buf][producer_cg][row][64]. Per step, each CTA bulk-copies
// its 2KB slice to all 8 cluster CTAs (cp.async.bulk shared::cluster, mbarrier tx).
// Data barrier: count 1 (+16KB expect_tx, 8 tx events). Free barrier: count 8 (backpressure).
__global__ void __launch_bounds__(512, 1) __cluster_dims__(8, 1, 1)
rnn_kernel(const float* __restrict__ Wh) {
    float* hsm = reinterpret_cast<float*>(dsm);
    float* part = reinterpret_cast<float*>(dsm + PART_OFF);
    float* stage = reinterpret_cast<float*>(dsm + STAGE_OFF);
    __shared__ __align__(8) unsigned long long bars[4];  // data0,data1,free0,free1

    int tid = threadIdx.x;
    int cg = blockIdx.x & 7;          // colgroup = cluster rank
    int rg = blockIdx.x >> 3;         // rowgroup
    int r0 = rg << 3;
    int lane = tid & 31;
    int w = tid >> 5;                 // 16 warps
    int ks = w & 7;                   // k-slice (64 wide)
    int ch = w >> 3;                  // col half
    int gcol = cg * 64 + ch * 32 + lane;

    // Wh slice in registers (f32x2 pairs): Wh[ks*64 .. +64][gcol]
    unsigned long long wreg[32];
    #pragma unroll
    for (int j2 = 0; j2 < 32; ++j2) {
        int k = ks * 64 + j2 * 2;
        float lo = Wh[(size_t)k * HDIM + gcol];
        float hi = Wh[(size_t)(k + 1) * HDIM + gcol];
        asm("mov.b64 %0, {%1, %2};" : "=l"(wreg[j2]) : "f"(lo), "f"(hi));
    }

    uint32_t hsm_u   = (uint32_t)__cvta_generic_to_shared(hsm);
    uint32_t stage_u = (uint32_t)__cvta_generic_to_shared(stage);
    uint32_t bars_u  = (uint32_t)__cvta_generic_to_shared(&bars[0]);

    // peer addresses (only tid 0 uses them)
    uint32_t peer_hsm[8], peer_bar[8];
    if (tid == 0) {
        #pragma unroll
        for (int p = 0; p < 8; ++p) {
            peer_hsm[p] = mapa_u32(hsm_u, (uint32_t)p);
            peer_bar[p] = mapa_u32(bars_u, (uint32_t)p);
        }
        MBARRIER_INIT(bars_u + 0, 1);    // data0
        MBARRIER_INIT(bars_u + 8, 1);    // data1
        MBARRIER_INIT(bars_u + 16, 8);   // free0
        MBARRIER_INIT(bars_u + 24, 8);   // free1
        asm volatile("fence.proxy.async;" ::: "memory");
        MBARRIER_EXPECT_TX(bars_u + 0, 0);        // pre-complete data0 phase0
        MBARRIER_EXPECT_TX(bars_u + 8, 16384);    // arm data1 for step 1
        #pragma unroll
        for (int i = 0; i < 8; ++i) MBARRIER_ARRIVE_LOCAL(bars_u + 24);  // free1 phase0
    }

    // fill hsm[0][cg'][row][16xfloat4] from g_h[0]
    {
        const float* h0 = g_h[0] + (size_t)r0 * HDIM;
        float4* dst = reinterpret_cast<float4*>(hsm);
        #pragma unroll
        for (int i = 0; i < 2; ++i) {
            int q = tid + i * 512;               // 0..1023
            int cgp = q >> 7;                    // 16 f4 per row * 8 rows = 128 per cg
            int r = (q >> 4) & 7;
            int j4 = q & 15;
            dst[q] = *reinterpret_cast<const float4*>(h0 + (size_t)r * HDIM + cgp * 64 + j4 * 4);
        }
    }
    __syncthreads();
    asm volatile("barrier.cluster.arrive.aligned;" ::: "memory");
    asm volatile("barrier.cluster.wait.aligned;" ::: "memory");

    int orow = tid >> 6, ocol = tid & 63;
    int och = ocol >> 5, olane = ocol & 31;
    int gcol2 = cg * 64 + ocol;
    uint32_t phd0 = 0, phd1 = 0, phf0 = 0, phf1 = 0;

    for (int t = 0; t < TT; ++t) {
        int b = t & 1, wv = b ^ 1;
        float xw = g_xW[((size_t)(r0 + orow) * TT + t) * HDIM + gcol2];

        // wait this step's h data, then re-arm for t+2
        if (b == 0) { wait_parity(bars_u + 0, phd0); phd0 ^= 1; }
        else        { wait_parity(bars_u + 8, phd1); phd1 ^= 1; }
        if (tid == 0) MBARRIER_EXPECT_TX(bars_u + (uint32_t)b * 8, 16384);

        // compute partials: warp (ks,ch), rows 0..7, h from hsm[b][ks][r][*]
        const float* hb = hsm + (size_t)(b * 8 + ks) * 512;
        #pragma unroll
        for (int r = 0; r < 8; ++r) {
            const ulonglong2* hp = reinterpret_cast<const ulonglong2*>(hb + r * 64);
            unsigned long long a0 = 0ull, a1 = 0ull, a2 = 0ull, a3 = 0ull;
            #pragma unroll
            for (int jj = 0; jj < 16; jj += 2) {
                ulonglong2 v0 = hp[jj];
                ulonglong2 v1 = hp[jj + 1];
                FFMA2(a0, v0.x, wreg[2 * jj + 0]);
                FFMA2(a1, v0.y, wreg[2 * jj + 1]);
                FFMA2(a2, v1.x, wreg[2 * jj + 2]);
                FFMA2(a3, v1.y, wreg[2 * jj + 3]);
            }
            unsigned long long s01, s23, s;
            asm("add.rn.f32x2 %0, %1, %2;" : "=l"(s01) : "l"(a0), "l"(a1));
            asm("add.rn.f32x2 %0, %1, %2;" : "=l"(s23) : "l"(a2), "l"(a3));
            asm("add.rn.f32x2 %0, %1, %2;" : "=l"(s)   : "l"(s01), "l"(s23));
            float lo, hi;
            asm("mov.b64 {%0, %1}, %2;" : "=f"(lo), "=f"(hi) : "l"(s));
            part[((r * 2 + ch) * 8 + ks) * 32 + lane] = lo + hi;
        }
        __syncthreads();   // all reads of hsm[b] complete

        // signal buffer b free to all cluster CTAs
        if (tid == 0) {
            #pragma unroll
            for (int p = 0; p < 8; ++p)
                MBARRIER_ARRIVE_REMOTE(peer_bar[p] + 16u + (uint32_t)b * 8u);
        }

        // reduce + tanh + stage
        float acc = 0.f;
        #pragma unroll
        for (int k2 = 0; k2 < 8; ++k2)
            acc += part[((orow * 2 + och) * 8 + k2) * 32 + olane];
        float hn = tanhf(acc + xw);
        stage[orow * 64 + ocol] = hn;
        g_hsb[((size_t)(r0 + orow) * TT + t) * HDIM + gcol2] = __float2bfloat16(hn);
        __syncthreads();   // stage complete

        // push: wait buffer wv free, then bulk-copy stage to all 8 CTAs
        if (tid == 0) {
            if (wv == 0) { wait_parity(bars_u + 16, phf0); phf0 ^= 1; }
            else         { wait_parity(bars_u + 24, phf1); phf1 ^= 1; }
            asm volatile("fence.proxy.async.shared::cta;" ::: "memory");
            uint32_t doff = (uint32_t)wv * 16384u + (uint32_t)cg * 2048u;
            #pragma unroll
            for (int p = 0; p < 8; ++p) {
                asm volatile(
                    "cp.async.bulk.shared::cluster.shared::cta.mbarrier::complete_tx::bytes "
                    "[%0], [%1], %2, [%3];"
                    :: "r"(peer_hsm[p] + doff), "r"(stage_u), "r"(2048u),
                       "r"(peer_bar[p] + (uint32_t)wv * 8u) : "memory");
            }
        }
    }

    // drain final incoming pushes, then cluster exit barrier
    wait_parity(bars_u + 8, phd1);
    asm volatile("barrier.cluster.arrive.aligned;" ::: "memory");
    asm volatile("barrier.cluster.wait.aligned;" ::: "memory");
}

// ---------------- kernel 5: bf16 HMMA scores GEMM + exp-sum epilogue ----------------
__global__ void __launch_bounds__(256, 1) loss_kernel(const float* __restrict__ bout,
                                                      const int* __restrict__ captions,
                                                      float* __restrict__ out) {
    __nv_bfloat16* sA = reinterpret_cast<__nv_bfloat16*>(dsm);
    __nv_bfloat16* sB = reinterpret_cast<__nv_bfloat16*>(dsm + 128 * LDA * 2);
    __shared__ float biasS[128];
    __shared__ float s_red[256];
    __shared__ float warp_sum[8];

    int tid = threadIdx.x;
    int lane = tid & 31, w = tid >> 5;
    int wm = w >> 1, wn = w & 1;
    int g = lane >> 2, tig = lane & 3;
    int i0 = blockIdx.x * 128;

    const char* hsb_base = reinterpret_cast<const char*>(g_hsb);
    for (int u = tid; u < 8192; u += 256) {
        int r = u >> 6, q = u & 63;
        int gi = i0 + r; if (gi >= NT) gi = NT - 1;
        float4 v = *reinterpret_cast<const float4*>(hsb_base + ((size_t)gi * HDIM + q * 8) * 2);
        *reinterpret_cast<float4*>(reinterpret_cast<char*>(sA) + (size_t)r * LDA * 2 + q * 16) = v;
    }
    __syncthreads();

    uint32_t sA_u = (uint32_t)__cvta_generic_to_shared(sA);
    uint32_t sB_u = (uint32_t)__cvta_generic_to_shared(sB);

    int j = lane >> 3, i8 = lane & 7;
    int a_row    = wm * 32 + (j & 1) * 8 + i8;
    int a_coloff = (j >> 1) * 8;
    int b_rowoff = (j >> 1) * 8 + i8;
    int b_coloff = (j & 1) * 8;

    float s_slot[4] = {0.f, 0.f, 0.f, 0.f};

    for (int vt = 0; vt < NVT; ++vt) {
        int v0 = vt * 128;
        for (int u2 = tid; u2 < 2048; u2 += 256) {
            int n = u2 >> 4, q = u2 & 15;
            int v = v0 + n; if (v >= VOCAB) v = VOCAB - 1;
            uint32_t dst = sB_u + (uint32_t)(0 * BSTRIDE + n * LDB + q * 8) * 2;
            cp16(dst, reinterpret_cast<const char*>(g_Wb) + ((size_t)v * HDIM + q * 8) * 2);
        }
        cp_commit();
        if (tid < 128) {
            int v = v0 + tid;
            biasS[tid] = (v < VOCAB) ? bout[v] : -30.0f;
        }

        float acc[2][8][4];
        #pragma unroll
        for (int mt = 0; mt < 2; ++mt)
            #pragma unroll
            for (int nt = 0; nt < 8; ++nt)
                #pragma unroll
                for (int q = 0; q < 4; ++q) acc[mt][nt][q] = 0.f;

        for (int st = 0; st < NSTAGES; ++st) {
            if (st + 1 < NSTAGES) {
                int kc = (st + 1) * KSTAGE;
                int buf = (st + 1) & 1;
                for (int u2 = tid; u2 < 2048; u2 += 256) {
                    int n = u2 >> 4, q = u2 & 15;
                    int v = v0 + n; if (v >= VOCAB) v = VOCAB - 1;
                    uint32_t dst = sB_u + (uint32_t)(buf * BSTRIDE + n * LDB + q * 8) * 2;
                    cp16(dst, reinterpret_cast<const char*>(g_Wb) + ((size_t)v * HDIM + kc + q * 8) * 2);
                }
                cp_commit();
                cp_wait<1>();
            } else {
                cp_wait<0>();
            }
            __syncthreads();

            int buf = st & 1;
            uint32_t bbase = sB_u + (uint32_t)buf * BSTRIDE * 2;
            #pragma unroll
            for (int sub = 0; sub < KSTAGE / 16; ++sub) {
                int kA = st * KSTAGE + sub * 16;
                int kB = sub * 16;
                uint32_t a0[2], a1[2], a2[2], a3[2];
                #pragma unroll
                for (int mt = 0; mt < 2; ++mt) {
                    uint32_t addr = sA_u + (uint32_t)(((a_row + mt * 16) * LDA) + kA + a_coloff) * 2;
                    ldsm4(a0[mt], a1[mt], a2[mt], a3[mt], addr);
                }
                #pragma unroll
                for (int pair = 0; pair < 4; ++pair) {
                    int n0 = wn * 64 + pair * 16;
                    uint32_t addr = bbase + (uint32_t)(((n0 + b_rowoff) * LDB) + kB + b_coloff) * 2;
                    uint32_t b0, b1, b2, b3;
                    ldsm4(b0, b1, b2, b3, addr);
                    #pragma unroll
                    for (int mt = 0; mt < 2; ++mt) {
                        mma16816(acc[mt][pair * 2 + 0], a0[mt], a1[mt], a2[mt], a3[mt], b0, b1);
                        mma16816(acc[mt][pair * 2 + 1], a0[mt], a1[mt], a2[mt], a3[mt], b2, b3);
                    }
                }
            }
            __syncthreads();
        }

        #pragma unroll
        for (int mt = 0; mt < 2; ++mt)
            #pragma unroll
            for (int half = 0; half < 2; ++half) {
                float s = 0.f;
                #pragma unroll
                for (int nt = 0; nt < 8; ++nt) {
                    int cb = wn * 64 + nt * 8 + 2 * tig;
                    s += __expf(acc[mt][nt][half * 2 + 0] + biasS[cb]);
                    s += __expf(acc[mt][nt][half * 2 + 1] + biasS[cb + 1]);
                }
                s_slot[mt * 2 + half] += s;
            }
        __syncthreads();
    }

    #pragma unroll
    for (int k2 = 0; k2 < 4; ++k2) {
        float s = s_slot[k2];
        s += __shfl_xor_sync(0xffffffffu, s, 1);
        s += __shfl_xor_sync(0xffffffffu, s, 2);
        s_slot[k2] = s;
    }
    if (tig == 0) {
        #pragma unroll
        for (int k2 = 0; k2 < 4; ++k2) {
            int row = wm * 32 + (k2 >> 1) * 16 + (k2 & 1) * 8 + g;
            s_red[row * 2 + wn] = s_slot[k2];
        }
    }
    __syncthreads();

    float contrib = 0.f;
    if (tid < 128) {
        float st = s_red[tid * 2] + s_red[tid * 2 + 1];
        int i2 = i0 + tid;
        if (i2 < NT) {
            int n = i2 / TT, t = i2 - n * TT;
            int tg = captions[n * TFULL + t + 1];
            if (tg != 0) contrib = logf(st);
        }
    }
    #pragma unroll
    for (int off = 16; off; off >>= 1)
        contrib += __shfl_xor_sync(0xffffffffu, contrib, off);
    if (lane == 0) warp_sum[w] = contrib;
    __syncthreads();
    if (tid == 0) {
        float b = 0.f;
        #pragma unroll
        for (int q = 0; q < 8; ++q) b += warp_sum[q];
        atomicAdd(out, b * (1.0f / (float)NB));
    }
}

// ---------------- kernel 6: picked target scores ----------------
__global__ void __launch_bounds__(256) picked_kernel(const float* __restrict__ bout,
                                                     const int* __restrict__ captions,
                                                     float* __restrict__ out) {
    __shared__ float wsum[8];
    int lane = threadIdx.x & 31, w = threadIdx.x >> 5;
    int row = blockIdx.x * 8 + w;
    float c = 0.f;
    if (row < NT) {
        int n = row / TT, t = row - n * TT;
        int tg = captions[n * TFULL + t + 1];
        if (tg != 0) {
            const __nv_bfloat162* h2 = reinterpret_cast<const __nv_bfloat162*>(g_hsb + (size_t)row * HDIM);
            const __nv_bfloat162* w2 = reinterpret_cast<const __nv_bfloat162*>(g_Wb + (size_t)tg * HDIM);
            float acc = 0.f;
            #pragma unroll
            for (int q = 0; q < 8; ++q) {
                __nv_bfloat162 a = h2[lane + q * 32];
                __nv_bfloat162 b = w2[lane + q * 32];
                acc = fmaf(__bfloat162float(a.x), __bfloat162float(b.x), acc);
                acc = fmaf(__bfloat162float(a.y), __bfloat162float(b.y), acc);
            }
            #pragma unroll
            for (int off = 16; off; off >>= 1)
                acc += __shfl_xor_sync(0xffffffffu, acc, off);
            if (lane == 0) c = -(acc + bout[tg]) * (1.0f / (float)NB);
        }
    }
    if (lane == 0) wsum[w] = c;
    __syncthreads();
    if (threadIdx.x == 0) {
        float b = 0.f;
        #pragma unroll
        for (int q = 0; q < 8; ++q) b += wsum[q];
        if (b != 0.f) atomicAdd(out, b);
    }
}

// ---------------- launch ----------------
extern "C" void kernel_launch(void* const* d_in, const int* in_sizes, int n_in,
                              void* d_out, int out_size) {
    const float* feat   = (const float*)d_in[0];
    const float* W_proj = (const float*)d_in[1];
    const float* b_proj = (const float*)d_in[2];
    const float* W_emb  = (const float*)d_in[3];
    const float* Wx     = (const float*)d_in[4];
    const float* Wh     = (const float*)d_in[5];
    const float* b      = (const float*)d_in[6];
    const float* W_out  = (const float*)d_in[7];
    const float* b_out  = (const float*)d_in[8];
    const int*   caps   = (const int*)d_in[9];
    float* out = (float*)d_out;

    cudaFuncSetAttribute(loss_kernel, cudaFuncAttributeMaxDynamicSharedMemorySize, DSMEM);
    cudaFuncSetAttribute(xw_kernel,   cudaFuncAttributeMaxDynamicSharedMemorySize, XW_SMEM);
    cudaFuncSetAttribute(rnn_kernel,  cudaFuncAttributeMaxDynamicSharedMemorySize, RNN_SMEM);

    init_kernel<<<1, 32>>>(out);
    h0_kernel<<<dim3(4, 8), 256>>>(feat, W_proj, b_proj);
    wtrans_kernel<<<dim3(313, 17), 256>>>(W_out, Wx);
    xw_kernel<<<dim3(128, 4), 256, XW_SMEM>>>(caps, W_emb, b);
    rnn_kernel<<<64, 512, RNN_SMEM>>>(Wh);
    loss_kernel<<<128, 256, DSMEM>>>(b_out, caps, out);
    picked_kernel<<<2040, 256>>>(b_out, caps, out);
}